// round 16
// baseline (speedup 1.0000x reference)
#include <cuda_runtime.h>
#include <cuda_bf16.h>
#include <math_constants.h>
#include <cstdint>

#define BATCH 4
#define SEQT 4096
#define EMB 768
#define HD 64
#define BT (BATCH * SEQT)

typedef unsigned long long ull;

// Scratch (device globals: no allocation allowed)
__device__ __nv_bfloat16 g_qh[BT * HD], g_ql[BT * HD];
__device__ __nv_bfloat16 g_kh[BT * HD], g_kl[BT * HD];
__device__ __nv_bfloat16 g_vh[BT * HD], g_vl[BT * HD];   // transposed [d][tok]
__device__ __nv_bfloat16 g_wth[3 * 64 * EMB], g_wtl[3 * 64 * EMB];
__device__ float g_po[4][BT * HD];  // split-K partial numerators
__device__ float g_pm[4][BT];       // split-K partial row max
__device__ float g_pl[4][BT];       // split-K partial row sum

__device__ __forceinline__ uint32_t s2u(const void* p) {
    return (uint32_t)__cvta_generic_to_shared(p);
}
__device__ __forceinline__ void cp16(uint32_t dst, const void* src) {
    asm volatile("cp.async.ca.shared.global [%0], [%1], 16;" :: "r"(dst), "l"(src));
}

// ---- bf16 helpers ----
__device__ __forceinline__ void mmabf(float* c, const uint32_t* a, const uint32_t* b) {
    asm volatile(
        "mma.sync.aligned.m16n8k16.row.col.f32.bf16.bf16.f32 "
        "{%0,%1,%2,%3}, {%4,%5,%6,%7}, {%8,%9}, {%0,%1,%2,%3};"
        : "+f"(c[0]), "+f"(c[1]), "+f"(c[2]), "+f"(c[3])
        : "r"(a[0]), "r"(a[1]), "r"(a[2]), "r"(a[3]), "r"(b[0]), "r"(b[1]));
}
__device__ __forceinline__ void bfsplit(float v, __nv_bfloat16& h, __nv_bfloat16& l) {
    h = __float2bfloat16_rn(v);
    l = __float2bfloat16_rn(v - __bfloat162float(h));
}
__device__ __forceinline__ uint32_t bfpack(__nv_bfloat16 a, __nv_bfloat16 b) {
    unsigned short ua = *reinterpret_cast<unsigned short*>(&a);
    unsigned short ub = *reinterpret_cast<unsigned short*>(&b);
    return (uint32_t)ua | ((uint32_t)ub << 16);
}
__device__ __forceinline__ uint32_t packsplit(float a, float b, uint32_t& lopk) {
    __nv_bfloat16 ha, la, hb, lb;
    bfsplit(a, ha, la);
    bfsplit(b, hb, lb);
    lopk = bfpack(la, lb);
    return bfpack(ha, hb);
}

// ---------------------------------------------------------------------------
// W pre-split
// ---------------------------------------------------------------------------
__global__ __launch_bounds__(256) void wsplit_kernel(
    const float* __restrict__ Wq,
    const float* __restrict__ Wk,
    const float* __restrict__ Wv)
{
    int idx = blockIdx.x * 256 + threadIdx.x;
    int mat = idx / (64 * EMB);
    int rem = idx - mat * 64 * EMB;
    int n = rem / EMB;
    int k = rem - n * EMB;
    const float* W = (mat == 0) ? Wq : ((mat == 1) ? Wk : Wv);
    float v = W[(size_t)k * HD + n];
    __nv_bfloat16 h, l;
    bfsplit(v, h, l);
    g_wth[idx] = h;
    g_wtl[idx] = l;
}

// ---------------------------------------------------------------------------
// Fused projection, all-bf16 m16n8k16 3-term. M=64/CTA, 256 CTAs, 2/SM.
// 8 warps: wr=wid>>1 (16 rows), wc=wid&1 (96 cols).
// ---------------------------------------------------------------------------
#define XF_OFF 0          // 2 x 64*36 u32 fp32 x staging
#define XP_OFF 4608       // hi 64*20, lo 64*20
#define WP_OFF 7168       // 2 bufs x (hi 192*20 + lo 192*20)
#define PJ2_SMEM_U32 22528
#define PJ2_SMEM_BYTES (PJ2_SMEM_U32 * 4)

__device__ __forceinline__ void pj2_cp(uint32_t* smu, int buf,
                                       const float* __restrict__ x,
                                       int row0, int k0, int tid)
{
    uint32_t* xf = smu + XF_OFF + buf * 2304;
    #pragma unroll
    for (int t = 0; t < 2; t++) {
        int idx = tid + t * 256;
        int r = idx >> 3, c = idx & 7;
        cp16(s2u(xf + r * 36 + c * 4), &x[(size_t)(row0 + r) * EMB + k0 + c * 4]);
    }
    uint32_t* wp = smu + WP_OFF + buf * 7680;
    #pragma unroll
    for (int t = 0; t < 6; t++) {
        int idx = tid + t * 256;
        int pl = (idx >= 768) ? 1 : 0;
        int rem = idx - pl * 768;
        int row = rem >> 2, chunk = rem & 3;
        const __nv_bfloat16* src =
            (pl ? g_wtl : g_wth) + (size_t)row * EMB + k0 + chunk * 8;
        cp16(s2u(wp + pl * 3840 + row * 20 + chunk * 4), src);
    }
    asm volatile("cp.async.commit_group;" ::: "memory");
}

__global__ __launch_bounds__(256, 2) void proj_bf16_kernel(const float* __restrict__ x)
{
    extern __shared__ uint32_t smu[];
    const int tid = threadIdx.x;
    const int lane = tid & 31;
    const int wid = tid >> 5;
    const int wr = wid >> 1;
    const int wc = wid & 1;
    const int row0 = blockIdx.x * 64;
    const int g = lane >> 2;
    const int t4 = lane & 3;

    float C[12][4];
    #pragma unroll
    for (int nt = 0; nt < 12; nt++)
        #pragma unroll
        for (int i = 0; i < 4; i++) C[nt][i] = 0.0f;

    pj2_cp(smu, 0, x, row0, 0, tid);
    pj2_cp(smu, 1, x, row0, 32, tid);

    for (int s = 0; s < 24; s++) {
        const int buf = s & 1;

        if (s < 23) asm volatile("cp.async.wait_group 1;" ::: "memory");
        else        asm volatile("cp.async.wait_group 0;" ::: "memory");
        __syncthreads();

        // Batched convert: fp32 x tile -> bf16 hi/lo planes
        {
            const uint32_t* xf = smu + XF_OFF + buf * 2304;
            uint32_t* xph = smu + XP_OFF;
            uint32_t* xpl = smu + XP_OFF + 1280;
            #pragma unroll
            for (int t = 0; t < 2; t++) {
                int idx = tid + t * 256;
                int r = idx >> 3, c = idx & 7;
                float4 v = *reinterpret_cast<const float4*>(xf + r * 36 + c * 4);
                uint32_t lo0, lo1;
                uint32_t h0 = packsplit(v.x, v.y, lo0);
                uint32_t h1 = packsplit(v.z, v.w, lo1);
                xph[r * 20 + c * 2] = h0;
                xph[r * 20 + c * 2 + 1] = h1;
                xpl[r * 20 + c * 2] = lo0;
                xpl[r * 20 + c * 2 + 1] = lo1;
            }
        }
        __syncthreads();

        {
            const uint32_t* xph = smu + XP_OFF;
            const uint32_t* xpl = smu + XP_OFF + 1280;
            const uint32_t* wph = smu + WP_OFF + buf * 7680;
            const uint32_t* wpl = wph + 3840;
            #pragma unroll
            for (int ks = 0; ks < 2; ks++) {
                uint32_t ah[4], al[4];
                int ab = (wr * 16 + g) * 20 + ks * 8 + t4;
                ah[0] = xph[ab];       ah[1] = xph[ab + 160];
                ah[2] = xph[ab + 4];   ah[3] = xph[ab + 164];
                al[0] = xpl[ab];       al[1] = xpl[ab + 160];
                al[2] = xpl[ab + 4];   al[3] = xpl[ab + 164];
                #pragma unroll
                for (int nt = 0; nt < 12; nt++) {
                    int gcol = wc * 96 + nt * 8 + g;
                    int bb = gcol * 20 + ks * 8 + t4;
                    uint32_t bh[2] = {wph[bb], wph[bb + 4]};
                    uint32_t bl[2] = {wpl[bb], wpl[bb + 4]};
                    mmabf(C[nt], ah, bh);
                    mmabf(C[nt], ah, bl);
                    mmabf(C[nt], al, bh);
                }
            }
        }
        __syncthreads();

        if (s + 2 < 24)
            pj2_cp(smu, buf, x, row0, (s + 2) * 32, tid);
    }

    // Epilogue: bf16 hi/lo plane stores (q,k row-major; v transposed; q*0.125)
    #pragma unroll
    for (int nt = 0; nt < 12; nt++) {
        int gn = wc * 96 + nt * 8;
        int mat = gn >> 6;
        int col = (gn & 63) + t4 * 2;
        int row = row0 + wr * 16 + g;
        float c0 = C[nt][0], c1 = C[nt][1];
        float c2 = C[nt][2], c3 = C[nt][3];
        if (mat == 0) {
            uint32_t lo, hi;
            hi = packsplit(0.125f * c0, 0.125f * c1, lo);
            *reinterpret_cast<uint32_t*>(&g_qh[(size_t)row * HD + col]) = hi;
            *reinterpret_cast<uint32_t*>(&g_ql[(size_t)row * HD + col]) = lo;
            hi = packsplit(0.125f * c2, 0.125f * c3, lo);
            *reinterpret_cast<uint32_t*>(&g_qh[(size_t)(row + 8) * HD + col]) = hi;
            *reinterpret_cast<uint32_t*>(&g_ql[(size_t)(row + 8) * HD + col]) = lo;
        } else if (mat == 1) {
            uint32_t lo, hi;
            hi = packsplit(c0, c1, lo);
            *reinterpret_cast<uint32_t*>(&g_kh[(size_t)row * HD + col]) = hi;
            *reinterpret_cast<uint32_t*>(&g_kl[(size_t)row * HD + col]) = lo;
            hi = packsplit(c2, c3, lo);
            *reinterpret_cast<uint32_t*>(&g_kh[(size_t)(row + 8) * HD + col]) = hi;
            *reinterpret_cast<uint32_t*>(&g_kl[(size_t)(row + 8) * HD + col]) = lo;
        } else {
            int bb = row >> 12;
            int tok = row & (SEQT - 1);
            size_t b0 = (size_t)(bb * HD + col) * SEQT + tok;
            size_t b1 = b0 + SEQT;
            __nv_bfloat16 h, l;
            bfsplit(c0, h, l); g_vh[b0] = h;     g_vl[b0] = l;
            bfsplit(c1, h, l); g_vh[b1] = h;     g_vl[b1] = l;
            bfsplit(c2, h, l); g_vh[b0 + 8] = h; g_vl[b0 + 8] = l;
            bfsplit(c3, h, l); g_vh[b1 + 8] = h; g_vl[b1 + 8] = l;
        }
    }
}

// ---------------------------------------------------------------------------
// Flash attention (causal), FA2: 128-row Q tiles, each warp owns 16 full rows.
// grid (74, B), one full wave at 2 CTA/SM:
//   i0<16: qi=31-i0/4, np=4 | i0<46: qi=27-(i0-16)/3, np=3
//   i0<66: qi=17-(i0-46)/2, np=2 | else qi=7-(i0-66), np=1
// K-range in 64-token tiles: ntl = 2qi+2; diag tiles 2qi, 2qi+1.
// ---------------------------------------------------------------------------
#define PW 36
#define OFF_K 9216          // 2 bufs x 4608 (hi 2304 + lo 2304)
#define OFF_V 18432
#define ATTN_SMEM_U32 27648
#define ATTN_SMEM_BYTES (ATTN_SMEM_U32 * 4)

__device__ __forceinline__ void tile_cpb(uint32_t* smu, int buf, int kt,
    const __nv_bfloat16* Kh, const __nv_bfloat16* Kl,
    const __nv_bfloat16* Vh, const __nv_bfloat16* Vl, int tid)
{
    uint32_t* kb = smu + OFF_K + buf * 4608;
    uint32_t* vb = smu + OFF_V + buf * 4608;
    #pragma unroll
    for (int t = 0; t < 4; t++) {
        int idx = tid + t * 256;
        int pl = idx >> 9, rem = idx & 511, tok = rem >> 3, q = rem & 7;
        const __nv_bfloat16* s = (pl ? Kl : Kh) + (size_t)(kt * 64 + tok) * HD + q * 8;
        cp16(s2u(kb + pl * 2304 + tok * PW + q * 4), s);
    }
    #pragma unroll
    for (int t = 0; t < 4; t++) {
        int idx = tid + t * 256;
        int pl = idx >> 9, rem = idx & 511, d = rem >> 3, q = rem & 7;
        const __nv_bfloat16* s = (pl ? Vl : Vh) + (size_t)d * SEQT + kt * 64 + q * 8;
        cp16(s2u(vb + pl * 2304 + d * PW + q * 4), s);
    }
    asm volatile("cp.async.commit_group;" ::: "memory");
}

__global__ __launch_bounds__(256, 2) void attn_mma_kernel(float* __restrict__ out)
{
    extern __shared__ uint32_t smu[];

    const int tid = threadIdx.x;
    const int lane = tid & 31;
    const int wid = tid >> 5;           // 0..7 = m-warp
    const int g = lane >> 2;
    const int t4 = lane & 3;
    const int b = blockIdx.y;
    const int i0 = blockIdx.x;

    int qi, part, np;
    if (i0 < 16)      { qi = 31 - (i0 >> 2);            part = i0 & 3;  np = 4; }
    else if (i0 < 46) { int t = i0 - 16; qi = 27 - t / 3; part = t % 3; np = 3; }
    else if (i0 < 66) { int t = i0 - 46; qi = 17 - (t >> 1); part = t & 1; np = 2; }
    else              { qi = 7 - (i0 - 66);             part = 0;       np = 1; }
    const int ntl = 2 * qi + 2;
    const int k0t = (part * ntl) / np;
    const int k1t = ((part + 1) * ntl) / np - 1;
    const bool partial = (np > 1);
    const int diag0 = ntl - 2, diag1 = ntl - 1;

    const __nv_bfloat16* Kh = g_kh + (size_t)b * SEQT * HD;
    const __nv_bfloat16* Kl = g_kl + (size_t)b * SEQT * HD;
    const __nv_bfloat16* Vh = g_vh + (size_t)b * HD * SEQT;
    const __nv_bfloat16* Vl = g_vl + (size_t)b * HD * SEQT;

    tile_cpb(smu, k0t & 1, k0t, Kh, Kl, Vh, Vl, tid);
    if (k0t + 1 <= k1t)
        tile_cpb(smu, (k0t + 1) & 1, k0t + 1, Kh, Kl, Vh, Vl, tid);

    // Q tile: 128 rows, hi plane at smu[0..4607], lo at smu[4608..]
    {
        const __nv_bfloat16* Qh = g_qh + ((size_t)b * SEQT + qi * 128) * HD;
        const __nv_bfloat16* Ql = g_ql + ((size_t)b * SEQT + qi * 128) * HD;
        #pragma unroll
        for (int t = 0; t < 8; t++) {
            int idx = tid + t * 256;
            int pl = idx >> 10, rem = idx & 1023, row = rem >> 3, q = rem & 7;
            const __nv_bfloat16* src = (pl ? Ql : Qh) + (size_t)row * HD + q * 8;
            float4 v = *reinterpret_cast<const float4*>(src);
            *reinterpret_cast<float4*>(smu + pl * 4608 + row * PW + q * 4) = v;
        }
    }

    const int r0 = 16 * wid + g;
    float rm0 = -CUDART_INF_F, rm1 = -CUDART_INF_F;
    float O[8][4];
    float Osum[4];
    #pragma unroll
    for (int nt = 0; nt < 8; nt++)
        #pragma unroll
        for (int i = 0; i < 4; i++) O[nt][i] = 0.0f;
    #pragma unroll
    for (int i = 0; i < 4; i++) Osum[i] = 0.0f;

    const uint32_t onesv = (g == 0) ? 0x3F803F80u : 0u;
    const uint32_t bones[2] = {onesv, onesv};

    for (int kt = k0t; kt <= k1t; kt++) {
        uint32_t* Kb = smu + OFF_K + (kt & 1) * 4608;
        uint32_t* Vb = smu + OFF_V + (kt & 1) * 4608;

        if (kt < k1t) asm volatile("cp.async.wait_group 1;" ::: "memory");
        else          asm volatile("cp.async.wait_group 0;" ::: "memory");
        __syncthreads();

        // ---- S = Q K^T over 64 tokens (3-term bf16) ----
        float S[8][4];
        #pragma unroll
        for (int nt = 0; nt < 8; nt++)
            #pragma unroll
            for (int i = 0; i < 4; i++) S[nt][i] = 0.0f;

        #pragma unroll
        for (int ks = 0; ks < 4; ks++) {
            int ab = r0 * PW + 8 * ks + t4;
            uint32_t ah[4], al[4];
            ah[0] = smu[ab];            ah[1] = smu[ab + 8 * PW];
            ah[2] = smu[ab + 4];        ah[3] = smu[ab + 8 * PW + 4];
            al[0] = smu[4608 + ab];     al[1] = smu[4608 + ab + 8 * PW];
            al[2] = smu[4608 + ab + 4]; al[3] = smu[4608 + ab + 8 * PW + 4];
            #pragma unroll
            for (int nt = 0; nt < 8; nt++) {
                int tok = 8 * nt + g;
                int bb2 = tok * PW + 8 * ks + t4;
                uint32_t bh[2] = {Kb[bb2], Kb[bb2 + 4]};
                uint32_t bl[2] = {Kb[2304 + bb2], Kb[2304 + bb2 + 4]};
                mmabf(S[nt], ah, bh);
                mmabf(S[nt], ah, bl);
                mmabf(S[nt], al, bh);
            }
        }

        // ---- causal mask on the two diagonal tiles ----
        if (kt == diag0 || kt == diag1) {
            int coff = (kt == diag1) ? 64 : 0;
            #pragma unroll
            for (int nt = 0; nt < 8; nt++) {
                int colb = 8 * nt + 2 * t4 + coff;
                if (colb     > r0)     S[nt][0] = -CUDART_INF_F;
                if (colb + 1 > r0)     S[nt][1] = -CUDART_INF_F;
                if (colb     > r0 + 8) S[nt][2] = -CUDART_INF_F;
                if (colb + 1 > r0 + 8) S[nt][3] = -CUDART_INF_F;
            }
        }

        // ---- per-warp online softmax (full rows; no cross-warp traffic) ----
        float wm0 = fmaxf(fmaxf(S[0][0], S[0][1]), fmaxf(S[1][0], S[1][1]));
        wm0 = fmaxf(wm0, fmaxf(fmaxf(S[2][0], S[2][1]), fmaxf(S[3][0], S[3][1])));
        wm0 = fmaxf(wm0, fmaxf(fmaxf(S[4][0], S[4][1]), fmaxf(S[5][0], S[5][1])));
        wm0 = fmaxf(wm0, fmaxf(fmaxf(S[6][0], S[6][1]), fmaxf(S[7][0], S[7][1])));
        float wm1 = fmaxf(fmaxf(S[0][2], S[0][3]), fmaxf(S[1][2], S[1][3]));
        wm1 = fmaxf(wm1, fmaxf(fmaxf(S[2][2], S[2][3]), fmaxf(S[3][2], S[3][3])));
        wm1 = fmaxf(wm1, fmaxf(fmaxf(S[4][2], S[4][3]), fmaxf(S[5][2], S[5][3])));
        wm1 = fmaxf(wm1, fmaxf(fmaxf(S[6][2], S[6][3]), fmaxf(S[7][2], S[7][3])));
        wm0 = fmaxf(wm0, __shfl_xor_sync(0xffffffffu, wm0, 1));
        wm0 = fmaxf(wm0, __shfl_xor_sync(0xffffffffu, wm0, 2));
        wm1 = fmaxf(wm1, __shfl_xor_sync(0xffffffffu, wm1, 1));
        wm1 = fmaxf(wm1, __shfl_xor_sync(0xffffffffu, wm1, 2));

        float nm0 = fmaxf(rm0, wm0);
        float nm1 = fmaxf(rm1, wm1);
        float ne0 = (nm0 == -CUDART_INF_F) ? 0.0f : nm0;
        float ne1 = (nm1 == -CUDART_INF_F) ? 0.0f : nm1;
        float alpha0 = __expf(rm0 - ne0);
        float alpha1 = __expf(rm1 - ne1);
        rm0 = nm0; rm1 = nm1;

        // ---- p = exp(s - ne), pack S C-frags -> P A-frags (registers) ----
        uint32_t ph[4][4], pl2[4][4];
        #pragma unroll
        for (int ks = 0; ks < 4; ks++) {
            float p00 = __expf(S[2 * ks][0] - ne0);
            float p01 = __expf(S[2 * ks][1] - ne0);
            float p10 = __expf(S[2 * ks][2] - ne1);
            float p11 = __expf(S[2 * ks][3] - ne1);
            float p20 = __expf(S[2 * ks + 1][0] - ne0);
            float p21 = __expf(S[2 * ks + 1][1] - ne0);
            float p30 = __expf(S[2 * ks + 1][2] - ne1);
            float p31 = __expf(S[2 * ks + 1][3] - ne1);
            ph[ks][0] = packsplit(p00, p01, pl2[ks][0]);
            ph[ks][1] = packsplit(p10, p11, pl2[ks][1]);
            ph[ks][2] = packsplit(p20, p21, pl2[ks][2]);
            ph[ks][3] = packsplit(p30, p31, pl2[ks][3]);
        }

        // ---- rescale O / rowsum ----
        #pragma unroll
        for (int nt = 0; nt < 8; nt++) {
            O[nt][0] *= alpha0; O[nt][1] *= alpha0;
            O[nt][2] *= alpha1; O[nt][3] *= alpha1;
        }
        Osum[0] *= alpha0; Osum[2] *= alpha1;

        // ---- O += P @ V over all 64 tokens; rowsum via ones-column ----
        #pragma unroll
        for (int ks = 0; ks < 4; ks++) {
            mmabf(Osum, ph[ks], bones);
            mmabf(Osum, pl2[ks], bones);
            #pragma unroll
            for (int nt = 0; nt < 8; nt++) {
                int d = 8 * nt + g;
                int vb2 = d * PW + 8 * ks + t4;
                uint32_t bh[2] = {Vb[vb2], Vb[vb2 + 4]};
                uint32_t bl[2] = {Vb[2304 + vb2], Vb[2304 + vb2 + 4]};
                mmabf(O[nt], ph[ks], bh);
                mmabf(O[nt], ph[ks], bl);
                mmabf(O[nt], pl2[ks], bh);
            }
        }
        __syncthreads();

        if (kt + 2 <= k1t)
            tile_cpb(smu, (kt & 1), kt + 2, Kh, Kl, Vh, Vl, tid);
    }

    // ---- epilogue: rows complete per warp; no merge needed ----
    float rs0 = __shfl_sync(0xffffffffu, Osum[0], lane & 28);
    float rs1 = __shfl_sync(0xffffffffu, Osum[2], lane & 28);

    if (!partial) {
        float iv0 = 1.0f / rs0, iv1 = 1.0f / rs1;
        size_t row = (size_t)b * SEQT + qi * 128 + r0;
        #pragma unroll
        for (int nt = 0; nt < 8; nt++) {
            int c = 8 * nt + 2 * t4;
            *reinterpret_cast<float2*>(&out[row * HD + c]) =
                make_float2(O[nt][0] * iv0, O[nt][1] * iv0);
            *reinterpret_cast<float2*>(&out[(row + 8) * HD + c]) =
                make_float2(O[nt][2] * iv1, O[nt][3] * iv1);
        }
    } else {
        int gr = b * SEQT + qi * 128 + r0;
        #pragma unroll
        for (int nt = 0; nt < 8; nt++) {
            int c = 8 * nt + 2 * t4;
            *reinterpret_cast<float2*>(&g_po[part][(size_t)gr * HD + c]) =
                make_float2(O[nt][0], O[nt][1]);
            *reinterpret_cast<float2*>(&g_po[part][(size_t)(gr + 8) * HD + c]) =
                make_float2(O[nt][2], O[nt][3]);
        }
        if (t4 == 0) {
            g_pm[part][gr] = rm0;     g_pl[part][gr] = rs0;
            g_pm[part][gr + 8] = rm1; g_pl[part][gr + 8] = rs1;
        }
    }
}

// ---------------------------------------------------------------------------
// Combine split-K partials: rows with qi >= 8 (local row >= 1024).
// np = 4 for row >= 3584, 3 for row >= 2304, else 2.
// 4 batches x 3072 rows x 16 float4 -> 768 blocks.
// ---------------------------------------------------------------------------
__global__ __launch_bounds__(256) void combine_kernel(float* __restrict__ out)
{
    int idx = blockIdx.x * 256 + threadIdx.x;
    int hr = idx >> 4;
    int c4 = (idx & 15) << 2;
    int b = hr / 3072;
    int r = 1024 + (hr - b * 3072);
    int gr = b * SEQT + r;
    int np = (r >= 3584) ? 4 : ((r >= 2304) ? 3 : 2);

    float M = fmaxf(g_pm[0][gr], g_pm[1][gr]);
    if (np >= 3) M = fmaxf(M, g_pm[2][gr]);
    if (np == 4) M = fmaxf(M, g_pm[3][gr]);

    float den = 0.0f;
    float ax = 0.0f, ay = 0.0f, az = 0.0f, aw = 0.0f;
    #pragma unroll
    for (int j = 0; j < 4; j++) {
        if (j < np) {
            float e = __expf(g_pm[j][gr] - M);
            den += e * g_pl[j][gr];
            float4 v = *reinterpret_cast<float4*>(&g_po[j][(size_t)gr * HD + c4]);
            ax += e * v.x; ay += e * v.y; az += e * v.z; aw += e * v.w;
        }
    }
    float inv = 1.0f / den;
    *reinterpret_cast<float4*>(&out[(size_t)gr * HD + c4]) =
        make_float4(ax * inv, ay * inv, az * inv, aw * inv);
}

extern "C" void kernel_launch(void* const* d_in, const int* in_sizes, int n_in,
                              void* d_out, int out_size) {
    (void)in_sizes; (void)n_in; (void)out_size;
    const float* x  = (const float*)d_in[0];
    const float* Wk = (const float*)d_in[1];
    const float* Wq = (const float*)d_in[2];
    const float* Wv = (const float*)d_in[3];
    float* out = (float*)d_out;

    wsplit_kernel<<<576, 256>>>(Wq, Wk, Wv);

    cudaFuncSetAttribute(proj_bf16_kernel,
                         cudaFuncAttributeMaxDynamicSharedMemorySize,
                         PJ2_SMEM_BYTES);
    proj_bf16_kernel<<<BT / 64, 256, PJ2_SMEM_BYTES>>>(x);

    cudaFuncSetAttribute(attn_mma_kernel,
                         cudaFuncAttributeMaxDynamicSharedMemorySize,
                         ATTN_SMEM_BYTES);
    dim3 ag(74, BATCH);
    attn_mma_kernel<<<ag, 256, ATTN_SMEM_BYTES>>>(out);

    combine_kernel<<<768, 256>>>(out);
}

// round 17
// speedup vs baseline: 1.1153x; 1.1153x over previous
#include <cuda_runtime.h>
#include <cuda_fp16.h>
#include <math_constants.h>
#include <cstdint>

#define BATCH 4
#define SEQT 4096
#define EMB 768
#define HD 64
#define BT (BATCH * SEQT)

typedef unsigned long long ull;

// Scratch (device globals: no allocation allowed) — fp16 planes
__device__ __half g_qh[BT * HD], g_ql[BT * HD];
__device__ __half g_kh[BT * HD], g_kl[BT * HD];
__device__ __half g_vh[BT * HD], g_vl[BT * HD];   // transposed [d][tok]
__device__ __half g_wth[3 * 64 * EMB], g_wtl[3 * 64 * EMB];
__device__ float g_po[4][BT * HD];  // split-K partial numerators
__device__ float g_pm[4][BT];       // split-K partial row max
__device__ float g_pl[4][BT];       // split-K partial row sum

__device__ __forceinline__ uint32_t s2u(const void* p) {
    return (uint32_t)__cvta_generic_to_shared(p);
}
__device__ __forceinline__ void cp16(uint32_t dst, const void* src) {
    asm volatile("cp.async.ca.shared.global [%0], [%1], 16;" :: "r"(dst), "l"(src));
}

// ---- fp16 helpers ----
__device__ __forceinline__ void mmahf(float* c, const uint32_t* a, const uint32_t* b) {
    asm volatile(
        "mma.sync.aligned.m16n8k16.row.col.f32.f16.f16.f32 "
        "{%0,%1,%2,%3}, {%4,%5,%6,%7}, {%8,%9}, {%0,%1,%2,%3};"
        : "+f"(c[0]), "+f"(c[1]), "+f"(c[2]), "+f"(c[3])
        : "r"(a[0]), "r"(a[1]), "r"(a[2]), "r"(a[3]), "r"(b[0]), "r"(b[1]));
}
__device__ __forceinline__ void hfsplit(float v, __half& h, __half& l) {
    h = __float2half_rn(v);
    l = __float2half_rn(v - __half2float(h));
}
__device__ __forceinline__ uint32_t hfpack(__half a, __half b) {
    unsigned short ua = *reinterpret_cast<unsigned short*>(&a);
    unsigned short ub = *reinterpret_cast<unsigned short*>(&b);
    return (uint32_t)ua | ((uint32_t)ub << 16);
}
// hi/lo pair split (a -> low half, b -> high half)
__device__ __forceinline__ uint32_t packsplit(float a, float b, uint32_t& lopk) {
    __half ha, la, hb, lb;
    hfsplit(a, ha, la);
    hfsplit(b, hb, lb);
    lopk = hfpack(la, lb);
    return hfpack(ha, hb);
}
// single-plane fp16 pair pack (a -> low, b -> high)
__device__ __forceinline__ uint32_t packp(float a, float b) {
    uint32_t r;
    asm("cvt.rn.f16x2.f32 %0, %1, %2;" : "=r"(r) : "f"(b), "f"(a));
    return r;
}

// ---------------------------------------------------------------------------
// W pre-split (fp16 planes)
// ---------------------------------------------------------------------------
__global__ __launch_bounds__(256) void wsplit_kernel(
    const float* __restrict__ Wq,
    const float* __restrict__ Wk,
    const float* __restrict__ Wv)
{
    int idx = blockIdx.x * 256 + threadIdx.x;
    int mat = idx / (64 * EMB);
    int rem = idx - mat * 64 * EMB;
    int n = rem / EMB;
    int k = rem - n * EMB;
    const float* W = (mat == 0) ? Wq : ((mat == 1) ? Wk : Wv);
    float v = W[(size_t)k * HD + n];
    __half h, l;
    hfsplit(v, h, l);
    g_wth[idx] = h;
    g_wtl[idx] = l;
}

// ---------------------------------------------------------------------------
// Fused projection, fp16 m16n8k16 3-term. M=64/CTA, 256 CTAs, 2/SM.
// ---------------------------------------------------------------------------
#define XF_OFF 0
#define XP_OFF 4608
#define WP_OFF 7168
#define PJ2_SMEM_U32 22528
#define PJ2_SMEM_BYTES (PJ2_SMEM_U32 * 4)

__device__ __forceinline__ void pj2_cp(uint32_t* smu, int buf,
                                       const float* __restrict__ x,
                                       int row0, int k0, int tid)
{
    uint32_t* xf = smu + XF_OFF + buf * 2304;
    #pragma unroll
    for (int t = 0; t < 2; t++) {
        int idx = tid + t * 256;
        int r = idx >> 3, c = idx & 7;
        cp16(s2u(xf + r * 36 + c * 4), &x[(size_t)(row0 + r) * EMB + k0 + c * 4]);
    }
    uint32_t* wp = smu + WP_OFF + buf * 7680;
    #pragma unroll
    for (int t = 0; t < 6; t++) {
        int idx = tid + t * 256;
        int pl = (idx >= 768) ? 1 : 0;
        int rem = idx - pl * 768;
        int row = rem >> 2, chunk = rem & 3;
        const __half* src =
            (pl ? g_wtl : g_wth) + (size_t)row * EMB + k0 + chunk * 8;
        cp16(s2u(wp + pl * 3840 + row * 20 + chunk * 4), src);
    }
    asm volatile("cp.async.commit_group;" ::: "memory");
}

__global__ __launch_bounds__(256, 2) void proj_hf_kernel(const float* __restrict__ x)
{
    extern __shared__ uint32_t smu[];
    const int tid = threadIdx.x;
    const int lane = tid & 31;
    const int wid = tid >> 5;
    const int wr = wid >> 1;
    const int wc = wid & 1;
    const int row0 = blockIdx.x * 64;
    const int g = lane >> 2;
    const int t4 = lane & 3;

    float C[12][4];
    #pragma unroll
    for (int nt = 0; nt < 12; nt++)
        #pragma unroll
        for (int i = 0; i < 4; i++) C[nt][i] = 0.0f;

    pj2_cp(smu, 0, x, row0, 0, tid);
    pj2_cp(smu, 1, x, row0, 32, tid);

    for (int s = 0; s < 24; s++) {
        const int buf = s & 1;

        if (s < 23) asm volatile("cp.async.wait_group 1;" ::: "memory");
        else        asm volatile("cp.async.wait_group 0;" ::: "memory");
        __syncthreads();

        // Batched convert: fp32 x tile -> fp16 hi/lo planes
        {
            const uint32_t* xf = smu + XF_OFF + buf * 2304;
            uint32_t* xph = smu + XP_OFF;
            uint32_t* xpl = smu + XP_OFF + 1280;
            #pragma unroll
            for (int t = 0; t < 2; t++) {
                int idx = tid + t * 256;
                int r = idx >> 3, c = idx & 7;
                float4 v = *reinterpret_cast<const float4*>(xf + r * 36 + c * 4);
                uint32_t lo0, lo1;
                uint32_t h0 = packsplit(v.x, v.y, lo0);
                uint32_t h1 = packsplit(v.z, v.w, lo1);
                xph[r * 20 + c * 2] = h0;
                xph[r * 20 + c * 2 + 1] = h1;
                xpl[r * 20 + c * 2] = lo0;
                xpl[r * 20 + c * 2 + 1] = lo1;
            }
        }
        __syncthreads();

        {
            const uint32_t* xph = smu + XP_OFF;
            const uint32_t* xpl = smu + XP_OFF + 1280;
            const uint32_t* wph = smu + WP_OFF + buf * 7680;
            const uint32_t* wpl = wph + 3840;
            #pragma unroll
            for (int ks = 0; ks < 2; ks++) {
                uint32_t ah[4], al[4];
                int ab = (wr * 16 + g) * 20 + ks * 8 + t4;
                ah[0] = xph[ab];       ah[1] = xph[ab + 160];
                ah[2] = xph[ab + 4];   ah[3] = xph[ab + 164];
                al[0] = xpl[ab];       al[1] = xpl[ab + 160];
                al[2] = xpl[ab + 4];   al[3] = xpl[ab + 164];
                #pragma unroll
                for (int nt = 0; nt < 12; nt++) {
                    int gcol = wc * 96 + nt * 8 + g;
                    int bb = gcol * 20 + ks * 8 + t4;
                    uint32_t bh[2] = {wph[bb], wph[bb + 4]};
                    uint32_t bl[2] = {wpl[bb], wpl[bb + 4]};
                    mmahf(C[nt], ah, bh);
                    mmahf(C[nt], ah, bl);
                    mmahf(C[nt], al, bh);
                }
            }
        }
        __syncthreads();

        if (s + 2 < 24)
            pj2_cp(smu, buf, x, row0, (s + 2) * 32, tid);
    }

    // Epilogue: fp16 hi/lo plane stores (q,k row-major; v transposed; q*0.125)
    #pragma unroll
    for (int nt = 0; nt < 12; nt++) {
        int gn = wc * 96 + nt * 8;
        int mat = gn >> 6;
        int col = (gn & 63) + t4 * 2;
        int row = row0 + wr * 16 + g;
        float c0 = C[nt][0], c1 = C[nt][1];
        float c2 = C[nt][2], c3 = C[nt][3];
        if (mat == 0) {
            uint32_t lo, hi;
            hi = packsplit(0.125f * c0, 0.125f * c1, lo);
            *reinterpret_cast<uint32_t*>(&g_qh[(size_t)row * HD + col]) = hi;
            *reinterpret_cast<uint32_t*>(&g_ql[(size_t)row * HD + col]) = lo;
            hi = packsplit(0.125f * c2, 0.125f * c3, lo);
            *reinterpret_cast<uint32_t*>(&g_qh[(size_t)(row + 8) * HD + col]) = hi;
            *reinterpret_cast<uint32_t*>(&g_ql[(size_t)(row + 8) * HD + col]) = lo;
        } else if (mat == 1) {
            uint32_t lo, hi;
            hi = packsplit(c0, c1, lo);
            *reinterpret_cast<uint32_t*>(&g_kh[(size_t)row * HD + col]) = hi;
            *reinterpret_cast<uint32_t*>(&g_kl[(size_t)row * HD + col]) = lo;
            hi = packsplit(c2, c3, lo);
            *reinterpret_cast<uint32_t*>(&g_kh[(size_t)(row + 8) * HD + col]) = hi;
            *reinterpret_cast<uint32_t*>(&g_kl[(size_t)(row + 8) * HD + col]) = lo;
        } else {
            int bb = row >> 12;
            int tok = row & (SEQT - 1);
            size_t b0 = (size_t)(bb * HD + col) * SEQT + tok;
            size_t b1 = b0 + SEQT;
            __half h, l;
            hfsplit(c0, h, l); g_vh[b0] = h;     g_vl[b0] = l;
            hfsplit(c1, h, l); g_vh[b1] = h;     g_vl[b1] = l;
            hfsplit(c2, h, l); g_vh[b0 + 8] = h; g_vl[b0 + 8] = l;
            hfsplit(c3, h, l); g_vh[b1 + 8] = h; g_vl[b1 + 8] = l;
        }
    }
}

// ---------------------------------------------------------------------------
// Flash attention (causal), FA2: 128-row Q tiles, fp16.
// S = 3-term (Qhi/lo x Khi/lo). PV = single-plane fp16 P x dual-plane V.
// grid (74, B), tiering identical to R10.
// ---------------------------------------------------------------------------
#define PW 36
#define OFF_K 9216
#define OFF_V 18432
#define ATTN_SMEM_U32 27648
#define ATTN_SMEM_BYTES (ATTN_SMEM_U32 * 4)

__device__ __forceinline__ void tile_cpb(uint32_t* smu, int buf, int kt,
    const __half* Kh, const __half* Kl,
    const __half* Vh, const __half* Vl, int tid)
{
    uint32_t* kb = smu + OFF_K + buf * 4608;
    uint32_t* vb = smu + OFF_V + buf * 4608;
    #pragma unroll
    for (int t = 0; t < 4; t++) {
        int idx = tid + t * 256;
        int pl = idx >> 9, rem = idx & 511, tok = rem >> 3, q = rem & 7;
        const __half* s = (pl ? Kl : Kh) + (size_t)(kt * 64 + tok) * HD + q * 8;
        cp16(s2u(kb + pl * 2304 + tok * PW + q * 4), s);
    }
    #pragma unroll
    for (int t = 0; t < 4; t++) {
        int idx = tid + t * 256;
        int pl = idx >> 9, rem = idx & 511, d = rem >> 3, q = rem & 7;
        const __half* s = (pl ? Vl : Vh) + (size_t)d * SEQT + kt * 64 + q * 8;
        cp16(s2u(vb + pl * 2304 + d * PW + q * 4), s);
    }
    asm volatile("cp.async.commit_group;" ::: "memory");
}

__global__ __launch_bounds__(256, 2) void attn_mma_kernel(float* __restrict__ out)
{
    extern __shared__ uint32_t smu[];

    const int tid = threadIdx.x;
    const int lane = tid & 31;
    const int wid = tid >> 5;           // 0..7 = m-warp
    const int g = lane >> 2;
    const int t4 = lane & 3;
    const int b = blockIdx.y;
    const int i0 = blockIdx.x;

    int qi, part, np;
    if (i0 < 16)      { qi = 31 - (i0 >> 2);            part = i0 & 3;  np = 4; }
    else if (i0 < 46) { int t = i0 - 16; qi = 27 - t / 3; part = t % 3; np = 3; }
    else if (i0 < 66) { int t = i0 - 46; qi = 17 - (t >> 1); part = t & 1; np = 2; }
    else              { qi = 7 - (i0 - 66);             part = 0;       np = 1; }
    const int ntl = 2 * qi + 2;
    const int k0t = (part * ntl) / np;
    const int k1t = ((part + 1) * ntl) / np - 1;
    const bool partial = (np > 1);
    const int diag0 = ntl - 2, diag1 = ntl - 1;

    const __half* Kh = g_kh + (size_t)b * SEQT * HD;
    const __half* Kl = g_kl + (size_t)b * SEQT * HD;
    const __half* Vh = g_vh + (size_t)b * HD * SEQT;
    const __half* Vl = g_vl + (size_t)b * HD * SEQT;

    tile_cpb(smu, k0t & 1, k0t, Kh, Kl, Vh, Vl, tid);
    if (k0t + 1 <= k1t)
        tile_cpb(smu, (k0t + 1) & 1, k0t + 1, Kh, Kl, Vh, Vl, tid);

    // Q tile: 128 rows, hi plane at smu[0..4607], lo at smu[4608..]
    {
        const __half* Qh = g_qh + ((size_t)b * SEQT + qi * 128) * HD;
        const __half* Ql = g_ql + ((size_t)b * SEQT + qi * 128) * HD;
        #pragma unroll
        for (int t = 0; t < 8; t++) {
            int idx = tid + t * 256;
            int pl = idx >> 10, rem = idx & 1023, row = rem >> 3, q = rem & 7;
            const __half* src = (pl ? Ql : Qh) + (size_t)row * HD + q * 8;
            float4 v = *reinterpret_cast<const float4*>(src);
            *reinterpret_cast<float4*>(smu + pl * 4608 + row * PW + q * 4) = v;
        }
    }

    const int r0 = 16 * wid + g;
    float rm0 = -CUDART_INF_F, rm1 = -CUDART_INF_F;
    float O[8][4];
    float Osum[4];
    #pragma unroll
    for (int nt = 0; nt < 8; nt++)
        #pragma unroll
        for (int i = 0; i < 4; i++) O[nt][i] = 0.0f;
    #pragma unroll
    for (int i = 0; i < 4; i++) Osum[i] = 0.0f;

    const uint32_t onesv = (g == 0) ? 0x3C003C00u : 0u;  // fp16 1.0 pair
    const uint32_t bones[2] = {onesv, onesv};

    for (int kt = k0t; kt <= k1t; kt++) {
        uint32_t* Kb = smu + OFF_K + (kt & 1) * 4608;
        uint32_t* Vb = smu + OFF_V + (kt & 1) * 4608;

        if (kt < k1t) asm volatile("cp.async.wait_group 1;" ::: "memory");
        else          asm volatile("cp.async.wait_group 0;" ::: "memory");
        __syncthreads();

        // ---- S = Q K^T over 64 tokens (3-term fp16) ----
        float S[8][4];
        #pragma unroll
        for (int nt = 0; nt < 8; nt++)
            #pragma unroll
            for (int i = 0; i < 4; i++) S[nt][i] = 0.0f;

        #pragma unroll
        for (int ks = 0; ks < 4; ks++) {
            int ab = r0 * PW + 8 * ks + t4;
            uint32_t ah[4], al[4];
            ah[0] = smu[ab];            ah[1] = smu[ab + 8 * PW];
            ah[2] = smu[ab + 4];        ah[3] = smu[ab + 8 * PW + 4];
            al[0] = smu[4608 + ab];     al[1] = smu[4608 + ab + 8 * PW];
            al[2] = smu[4608 + ab + 4]; al[3] = smu[4608 + ab + 8 * PW + 4];
            #pragma unroll
            for (int nt = 0; nt < 8; nt++) {
                int tok = 8 * nt + g;
                int bb2 = tok * PW + 8 * ks + t4;
                uint32_t bh[2] = {Kb[bb2], Kb[bb2 + 4]};
                uint32_t bl[2] = {Kb[2304 + bb2], Kb[2304 + bb2 + 4]};
                mmahf(S[nt], ah, bh);
                mmahf(S[nt], ah, bl);
                mmahf(S[nt], al, bh);
            }
        }

        // ---- causal mask on the two diagonal tiles ----
        if (kt == diag0 || kt == diag1) {
            int coff = (kt == diag1) ? 64 : 0;
            #pragma unroll
            for (int nt = 0; nt < 8; nt++) {
                int colb = 8 * nt + 2 * t4 + coff;
                if (colb     > r0)     S[nt][0] = -CUDART_INF_F;
                if (colb + 1 > r0)     S[nt][1] = -CUDART_INF_F;
                if (colb     > r0 + 8) S[nt][2] = -CUDART_INF_F;
                if (colb + 1 > r0 + 8) S[nt][3] = -CUDART_INF_F;
            }
        }

        // ---- per-warp online softmax ----
        float wm0 = fmaxf(fmaxf(S[0][0], S[0][1]), fmaxf(S[1][0], S[1][1]));
        wm0 = fmaxf(wm0, fmaxf(fmaxf(S[2][0], S[2][1]), fmaxf(S[3][0], S[3][1])));
        wm0 = fmaxf(wm0, fmaxf(fmaxf(S[4][0], S[4][1]), fmaxf(S[5][0], S[5][1])));
        wm0 = fmaxf(wm0, fmaxf(fmaxf(S[6][0], S[6][1]), fmaxf(S[7][0], S[7][1])));
        float wm1 = fmaxf(fmaxf(S[0][2], S[0][3]), fmaxf(S[1][2], S[1][3]));
        wm1 = fmaxf(wm1, fmaxf(fmaxf(S[2][2], S[2][3]), fmaxf(S[3][2], S[3][3])));
        wm1 = fmaxf(wm1, fmaxf(fmaxf(S[4][2], S[4][3]), fmaxf(S[5][2], S[5][3])));
        wm1 = fmaxf(wm1, fmaxf(fmaxf(S[6][2], S[6][3]), fmaxf(S[7][2], S[7][3])));
        wm0 = fmaxf(wm0, __shfl_xor_sync(0xffffffffu, wm0, 1));
        wm0 = fmaxf(wm0, __shfl_xor_sync(0xffffffffu, wm0, 2));
        wm1 = fmaxf(wm1, __shfl_xor_sync(0xffffffffu, wm1, 1));
        wm1 = fmaxf(wm1, __shfl_xor_sync(0xffffffffu, wm1, 2));

        float nm0 = fmaxf(rm0, wm0);
        float nm1 = fmaxf(rm1, wm1);
        float ne0 = (nm0 == -CUDART_INF_F) ? 0.0f : nm0;
        float ne1 = (nm1 == -CUDART_INF_F) ? 0.0f : nm1;
        float alpha0 = __expf(rm0 - ne0);
        float alpha1 = __expf(rm1 - ne1);
        rm0 = nm0; rm1 = nm1;

        // ---- p = exp(s - ne), single-plane fp16 pack -> P A-frags ----
        uint32_t ph[4][4];
        #pragma unroll
        for (int ks = 0; ks < 4; ks++) {
            float p00 = __expf(S[2 * ks][0] - ne0);
            float p01 = __expf(S[2 * ks][1] - ne0);
            float p10 = __expf(S[2 * ks][2] - ne1);
            float p11 = __expf(S[2 * ks][3] - ne1);
            float p20 = __expf(S[2 * ks + 1][0] - ne0);
            float p21 = __expf(S[2 * ks + 1][1] - ne0);
            float p30 = __expf(S[2 * ks + 1][2] - ne1);
            float p31 = __expf(S[2 * ks + 1][3] - ne1);
            ph[ks][0] = packp(p00, p01);
            ph[ks][1] = packp(p10, p11);
            ph[ks][2] = packp(p20, p21);
            ph[ks][3] = packp(p30, p31);
        }

        // ---- rescale O / rowsum ----
        #pragma unroll
        for (int nt = 0; nt < 8; nt++) {
            O[nt][0] *= alpha0; O[nt][1] *= alpha0;
            O[nt][2] *= alpha1; O[nt][3] *= alpha1;
        }
        Osum[0] *= alpha0; Osum[2] *= alpha1;

        // ---- O += P @ (Vh + Vl); rowsum via ones-column ----
        #pragma unroll
        for (int ks = 0; ks < 4; ks++) {
            mmahf(Osum, ph[ks], bones);
            #pragma unroll
            for (int nt = 0; nt < 8; nt++) {
                int d = 8 * nt + g;
                int vb2 = d * PW + 8 * ks + t4;
                uint32_t bh[2] = {Vb[vb2], Vb[vb2 + 4]};
                uint32_t bl[2] = {Vb[2304 + vb2], Vb[2304 + vb2 + 4]};
                mmahf(O[nt], ph[ks], bh);
                mmahf(O[nt], ph[ks], bl);
            }
        }
        __syncthreads();

        if (kt + 2 <= k1t)
            tile_cpb(smu, (kt & 1), kt + 2, Kh, Kl, Vh, Vl, tid);
    }

    // ---- epilogue: rows complete per warp; no merge needed ----
    float rs0 = __shfl_sync(0xffffffffu, Osum[0], lane & 28);
    float rs1 = __shfl_sync(0xffffffffu, Osum[2], lane & 28);

    if (!partial) {
        float iv0 = 1.0f / rs0, iv1 = 1.0f / rs1;
        size_t row = (size_t)b * SEQT + qi * 128 + r0;
        #pragma unroll
        for (int nt = 0; nt < 8; nt++) {
            int c = 8 * nt + 2 * t4;
            *reinterpret_cast<float2*>(&out[row * HD + c]) =
                make_float2(O[nt][0] * iv0, O[nt][1] * iv0);
            *reinterpret_cast<float2*>(&out[(row + 8) * HD + c]) =
                make_float2(O[nt][2] * iv1, O[nt][3] * iv1);
        }
    } else {
        int gr = b * SEQT + qi * 128 + r0;
        #pragma unroll
        for (int nt = 0; nt < 8; nt++) {
            int c = 8 * nt + 2 * t4;
            *reinterpret_cast<float2*>(&g_po[part][(size_t)gr * HD + c]) =
                make_float2(O[nt][0], O[nt][1]);
            *reinterpret_cast<float2*>(&g_po[part][(size_t)(gr + 8) * HD + c]) =
                make_float2(O[nt][2], O[nt][3]);
        }
        if (t4 == 0) {
            g_pm[part][gr] = rm0;     g_pl[part][gr] = rs0;
            g_pm[part][gr + 8] = rm1; g_pl[part][gr + 8] = rs1;
        }
    }
}

// ---------------------------------------------------------------------------
// Combine split-K partials (unchanged)
// ---------------------------------------------------------------------------
__global__ __launch_bounds__(256) void combine_kernel(float* __restrict__ out)
{
    int idx = blockIdx.x * 256 + threadIdx.x;
    int hr = idx >> 4;
    int c4 = (idx & 15) << 2;
    int b = hr / 3072;
    int r = 1024 + (hr - b * 3072);
    int gr = b * SEQT + r;
    int np = (r >= 3584) ? 4 : ((r >= 2304) ? 3 : 2);

    float M = fmaxf(g_pm[0][gr], g_pm[1][gr]);
    if (np >= 3) M = fmaxf(M, g_pm[2][gr]);
    if (np == 4) M = fmaxf(M, g_pm[3][gr]);

    float den = 0.0f;
    float ax = 0.0f, ay = 0.0f, az = 0.0f, aw = 0.0f;
    #pragma unroll
    for (int j = 0; j < 4; j++) {
        if (j < np) {
            float e = __expf(g_pm[j][gr] - M);
            den += e * g_pl[j][gr];
            float4 v = *reinterpret_cast<float4*>(&g_po[j][(size_t)gr * HD + c4]);
            ax += e * v.x; ay += e * v.y; az += e * v.z; aw += e * v.w;
        }
    }
    float inv = 1.0f / den;
    *reinterpret_cast<float4*>(&out[(size_t)gr * HD + c4]) =
        make_float4(ax * inv, ay * inv, az * inv, aw * inv);
}

extern "C" void kernel_launch(void* const* d_in, const int* in_sizes, int n_in,
                              void* d_out, int out_size) {
    (void)in_sizes; (void)n_in; (void)out_size;
    const float* x  = (const float*)d_in[0];
    const float* Wk = (const float*)d_in[1];
    const float* Wq = (const float*)d_in[2];
    const float* Wv = (const float*)d_in[3];
    float* out = (float*)d_out;

    wsplit_kernel<<<576, 256>>>(Wq, Wk, Wv);

    cudaFuncSetAttribute(proj_hf_kernel,
                         cudaFuncAttributeMaxDynamicSharedMemorySize,
                         PJ2_SMEM_BYTES);
    proj_hf_kernel<<<BT / 64, 256, PJ2_SMEM_BYTES>>>(x);

    cudaFuncSetAttribute(attn_mma_kernel,
                         cudaFuncAttributeMaxDynamicSharedMemorySize,
                         ATTN_SMEM_BYTES);
    dim3 ag(74, BATCH);
    attn_mma_kernel<<<ag, 256, ATTN_SMEM_BYTES>>>(out);

    combine_kernel<<<768, 256>>>(out);
}